// round 5
// baseline (speedup 1.0000x reference)
#include <cuda_runtime.h>

#define NPTS    8192
#define NCODES  16384
#define DIM     64

#define PB      32            // points per block
#define CT      512           // codes per tile
#define CHD     16            // d-rows per chunk
#define NCHUNK  ((NCODES / CT) * (DIM / CHD))   // 32 tiles * 4 phases = 128
#define RING    3

// output layout (floats)
#define OFF_ZQ     0
#define OFF_LOSS   524288
#define OFF_IDX    524289
#define OFF_NUNIQ  532481
#define OFF_USAGE  532482
#define OFF_TOTAL  548866

__device__ int    g_idx[NPTS];
__device__ float  g_b[NCODES];
__device__ float  g_eT[DIM * NCODES];   // transposed codebook [d][k]
__device__ double g_loss;

// ---------------------------------------------------------------------------
// packed f32x2 helpers
// ---------------------------------------------------------------------------
#define PACK_DUP(dst, f) \
    asm("mov.b64 %0, {%1, %1};" : "=l"(dst) : "f"(f))
#define FMA2(acc, a, b) \
    asm("fma.rn.f32x2 %0, %1, %2, %0;" : "+l"(acc) : "l"(a), "l"(b))
#define UNPACK2(lo, hi, v) \
    asm("mov.b64 {%0, %1}, %2;" : "=f"(lo), "=f"(hi) : "l"(v))

__device__ __forceinline__ void cp_async16(void* smem_dst, const void* gmem_src) {
    unsigned s = (unsigned)__cvta_generic_to_shared(smem_dst);
    asm volatile("cp.async.cg.shared.global [%0], [%1], 16;" :: "r"(s), "l"(gmem_src));
}
__device__ __forceinline__ void cp_commit() {
    asm volatile("cp.async.commit_group;");
}
__device__ __forceinline__ void cp_wait1() {
    asm volatile("cp.async.wait_group 1;");
}

// ---------------------------------------------------------------------------
// 0) init
// ---------------------------------------------------------------------------
__global__ void vq_init(float* out) {
    int t = blockIdx.x * blockDim.x + threadIdx.x;
    if (t < NCODES) out[OFF_USAGE + t] = 0.0f;
    if (t == 0) g_loss = 0.0;
}

// ---------------------------------------------------------------------------
// 1) transpose codebook [k][d] -> g_eT [d][k]
// ---------------------------------------------------------------------------
__global__ void vq_transpose(const float* __restrict__ emb) {
    __shared__ float t[32][33];
    int kb = blockIdx.x * 32;
    int db = blockIdx.y * 32;
    int x = threadIdx.x, y = threadIdx.y;  // 32 x 8
    for (int yy = y; yy < 32; yy += 8)
        t[yy][x] = emb[(size_t)(kb + yy) * DIM + db + x];
    __syncthreads();
    for (int yy = y; yy < 32; yy += 8)
        g_eT[(size_t)(db + yy) * NCODES + kb + x] = t[x][yy];
}

// ---------------------------------------------------------------------------
// 2) b_k = sum_d e[k][d]^2
// ---------------------------------------------------------------------------
__global__ void vq_codenorm(const float* __restrict__ emb) {
    int k = blockIdx.x * blockDim.x + threadIdx.x;
    if (k >= NCODES) return;
    const float* row = emb + (size_t)k * DIM;
    float s = 0.0f;
#pragma unroll 8
    for (int d = 0; d < DIM; ++d) s = fmaf(row[d], row[d], s);
    g_b[k] = s;
}

// ---------------------------------------------------------------------------
// 3) main argmin kernel (fused zq/loss epilogue)
//    256 threads, 2 CTAs/SM. 32 points x 16384 codes.
//    4 point-groups (8 pts) x 64 code-lanes; thread tile 8 pts x 8 codes.
//    es: 3-deep ring of (16 d-rows x 512 codes) chunks, cp.async 1 ahead.
// ---------------------------------------------------------------------------
#define ES_FLOATS   (RING * CHD * CT)   // 24576
#define ZS_STRIDE   36
#define ZS_FLOATS   (DIM * ZS_STRIDE)   // 2304
#define OFF_ES      0
#define OFF_ZS      ES_FLOATS
#define OFF_SBB     (OFF_ZS + ZS_FLOATS)
#define OFF_SA      (OFF_SBB + 2 * CT)
#define SM_FLOATS   (OFF_SA + PB)       // 27936 floats = 111744 B

__device__ __forceinline__ void issue_chunk(float* es, float* sb, int idx, int tid) {
    const int slot = idx % RING;
    const int tile = idx >> 2;
    const int d0   = (idx & 3) * CHD;
#pragma unroll
    for (int i = 0; i < 8; ++i) {
        int u   = tid + i * 256;      // 2048 units of 16B
        int row = u >> 7;             // 0..15
        int col = (u & 127) * 4;      // float col 0..508
        cp_async16(es + slot * (CHD * CT) + row * CT + col,
                   g_eT + (size_t)(d0 + row) * NCODES + tile * CT + col);
    }
    if ((idx & 3) == 0 && tid < 128) {
        cp_async16(sb + (tile & 1) * CT + tid * 4, g_b + tile * CT + tid * 4);
    }
}

__global__ __launch_bounds__(256, 2)
void vq_argmin(const float* __restrict__ z, const float* __restrict__ emb,
               float* __restrict__ out) {
    extern __shared__ float smem[];
    float* es = smem + OFF_ES;
    float* zs = smem + OFF_ZS;
    float* sb = smem + OFF_SBB;
    float* sa = smem + OFF_SA;

    const int tid = threadIdx.x;
    const int grp = tid >> 6;          // 0..3 : points grp*8..+7
    const int l64 = tid & 63;          // codes 4*l64 and 4*l64+256 within tile

    const int pbase   = blockIdx.x * PB;
    const int bb      = pbase >> 10;
    const int posbase = pbase & 1023;

    // prologue: 2 chunks in flight
    issue_chunk(es, sb, 0, tid); cp_commit();
    issue_chunk(es, sb, 1, tid); cp_commit();

    // stage z: zs[d][pos], pos < 32
    for (int t = tid; t < DIM * PB; t += 256) {
        int d = t >> 5, pos = t & 31;
        zs[d * ZS_STRIDE + pos] =
            z[(size_t)bb * 65536 + (size_t)d * 1024 + posbase + pos];
    }
    __syncthreads();

    // a_p = sum_d fl(z^2), strictly sequential d (match jnp.sum order)
    if (tid < PB) {
        float s = 0.0f;
        for (int d = 0; d < DIM; ++d) {
            float v = zs[d * ZS_STRIDE + tid];
            s = __fadd_rn(s, __fmul_rn(v, v));
        }
        sa[tid] = s;
    }
    __syncthreads();

    float a_r[8];
#pragma unroll
    for (int i = 0; i < 8; ++i) a_r[i] = sa[grp * 8 + i];

    float bestd[8];
    int   bestk[8];
#pragma unroll
    for (int i = 0; i < 8; ++i) { bestd[i] = __int_as_float(0x7f800000); bestk[i] = 0; }

    unsigned long long acc[8][4];
#pragma unroll
    for (int i = 0; i < 8; ++i)
#pragma unroll
        for (int j = 0; j < 4; ++j) acc[i][j] = 0ULL;

    const float* zbase = zs + grp * 8;

    for (int c = 0; c < NCHUNK; ++c) {
        cp_wait1();            // chunk c's group retired (1 pending = c+1)
        __syncthreads();       // chunk c visible to all; all done with c-1
        if (c + 2 < NCHUNK) issue_chunk(es, sb, c + 2, tid);
        cp_commit();           // always commit (possibly empty group)

        const float* ebase = es + (c % RING) * (CHD * CT) + l64 * 4;
        const int d0 = (c & 3) * CHD;

#pragma unroll 4
        for (int dd = 0; dd < CHD; ++dd) {
            const float* zrow = zbase + (d0 + dd) * ZS_STRIDE;
            const float4 za = *(const float4*)(zrow);
            const float4 zb = *(const float4*)(zrow + 4);
            unsigned long long zz[8];
            PACK_DUP(zz[0], za.x); PACK_DUP(zz[1], za.y);
            PACK_DUP(zz[2], za.z); PACK_DUP(zz[3], za.w);
            PACK_DUP(zz[4], zb.x); PACK_DUP(zz[5], zb.y);
            PACK_DUP(zz[6], zb.z); PACK_DUP(zz[7], zb.w);

            const float* erow = ebase + dd * CT;
            const ulonglong2 eA = *(const ulonglong2*)(erow);
            const ulonglong2 eB = *(const ulonglong2*)(erow + 256);

#pragma unroll
            for (int i = 0; i < 8; ++i) {
                FMA2(acc[i][0], zz[i], eA.x);
                FMA2(acc[i][1], zz[i], eA.y);
                FMA2(acc[i][2], zz[i], eB.x);
                FMA2(acc[i][3], zz[i], eB.y);
            }
        }

        if ((c & 3) == 3) {
            // tile epilogue: dist = fl( fl(a+b) - 2c ), ascending k in-thread
            const int tile  = c >> 2;
            const int kbase = tile * CT;
            const float* sbc = sb + (tile & 1) * CT + l64 * 4;
            const float4 bA = *(const float4*)(sbc);
            const float4 bB = *(const float4*)(sbc + 256);
            const int kA = kbase + l64 * 4;
            const int kB = kA + 256;
#pragma unroll
            for (int i = 0; i < 8; ++i) {
                float c0, c1, c2, c3;
                UNPACK2(c0, c1, acc[i][0]);
                UNPACK2(c2, c3, acc[i][1]);
                float d0v = fmaf(-2.0f, c0, __fadd_rn(a_r[i], bA.x));
                float d1v = fmaf(-2.0f, c1, __fadd_rn(a_r[i], bA.y));
                float d2v = fmaf(-2.0f, c2, __fadd_rn(a_r[i], bA.z));
                float d3v = fmaf(-2.0f, c3, __fadd_rn(a_r[i], bA.w));
                if (d0v < bestd[i]) { bestd[i] = d0v; bestk[i] = kA;     }
                if (d1v < bestd[i]) { bestd[i] = d1v; bestk[i] = kA + 1; }
                if (d2v < bestd[i]) { bestd[i] = d2v; bestk[i] = kA + 2; }
                if (d3v < bestd[i]) { bestd[i] = d3v; bestk[i] = kA + 3; }
                UNPACK2(c0, c1, acc[i][2]);
                UNPACK2(c2, c3, acc[i][3]);
                d0v = fmaf(-2.0f, c0, __fadd_rn(a_r[i], bB.x));
                d1v = fmaf(-2.0f, c1, __fadd_rn(a_r[i], bB.y));
                d2v = fmaf(-2.0f, c2, __fadd_rn(a_r[i], bB.z));
                d3v = fmaf(-2.0f, c3, __fadd_rn(a_r[i], bB.w));
                if (d0v < bestd[i]) { bestd[i] = d0v; bestk[i] = kB;     }
                if (d1v < bestd[i]) { bestd[i] = d1v; bestk[i] = kB + 1; }
                if (d2v < bestd[i]) { bestd[i] = d2v; bestk[i] = kB + 2; }
                if (d3v < bestd[i]) { bestd[i] = d3v; bestk[i] = kB + 3; }
                acc[i][0] = 0ULL; acc[i][1] = 0ULL;
                acc[i][2] = 0ULL; acc[i][3] = 0ULL;
            }
        }
    }

    // cross-thread reduction with (d, k) lexicographic min (es region reused)
    __syncthreads();
    float* rd = smem;                       // [0,   2048)
    int*   ri = (int*)(smem + 2048);        // [2048,4096)
    int*   ki = (int*)(smem + 4096);        // [4096,4128) winner idx per point
    double* ld = (double*)(smem + 4352);    // [4352,4864) 256 doubles
#pragma unroll
    for (int i = 0; i < 8; ++i) {
        rd[tid * 8 + i] = bestd[i];
        ri[tid * 8 + i] = bestk[i];
    }
    __syncthreads();

    if (tid < PB) {
        int p  = tid;
        int mg = p >> 3;
        int mi = p & 7;
        float bd = __int_as_float(0x7f800000);
        int   bk = 0x7fffffff;
        for (int t = 0; t < 64; ++t) {
            int   t2 = (mg * 64 + t) * 8 + mi;
            float dd = rd[t2];
            int   kk = ri[t2];
            if (dd < bd || (dd == bd && kk < bk)) { bd = dd; bk = kk; }
        }
        ki[p] = bk;
        g_idx[pbase + p] = bk;
        out[OFF_IDX + pbase + p] = (float)bk;
        out[OFF_USAGE + bk] = 1.0f;          // idempotent scatter
    }
    __syncthreads();

    // fused z_q gather + loss: thread owns point p = tid&31, d = (tid>>5)+8i
    {
        const int p = tid & 31;
        const int k = ki[p];
        const float* erow = emb + (size_t)k * DIM;
        double lacc = 0.0;
#pragma unroll
        for (int i = 0; i < 8; ++i) {
            int d = (tid >> 5) + i * 8;
            float e  = erow[d];
            float zv = zs[d * ZS_STRIDE + p];
            out[OFF_ZQ + (size_t)bb * 65536 + (size_t)d * 1024 + posbase + p] = e;
            float diff = e - zv;
            lacc += (double)diff * (double)diff;
        }
        ld[tid] = lacc;
    }
    __syncthreads();
    for (int s = 128; s > 0; s >>= 1) {
        if (tid < s) ld[tid] += ld[tid + s];
        __syncthreads();
    }
    if (tid == 0) atomicAdd(&g_loss, ld[0]);
}

// ---------------------------------------------------------------------------
// 4) finalize
// ---------------------------------------------------------------------------
__global__ void vq_finalize(float* out) {
    __shared__ float sf[512];
    float s = 0.0f;
    for (int t = threadIdx.x; t < NCODES; t += 512) s += out[OFF_USAGE + t];
    sf[threadIdx.x] = s;
    __syncthreads();
    for (int st = 256; st > 0; st >>= 1) {
        if (threadIdx.x < st) sf[threadIdx.x] += sf[threadIdx.x + st];
        __syncthreads();
    }
    if (threadIdx.x == 0) {
        float total = sf[0];
        out[OFF_NUNIQ] = total;
        out[OFF_TOTAL] = total / (float)NCODES;
        float m = (float)(g_loss / 524288.0);
        out[OFF_LOSS] = m + 0.25f * m;
    }
}

// ---------------------------------------------------------------------------
extern "C" void kernel_launch(void* const* d_in, const int* in_sizes, int n_in,
                              void* d_out, int out_size) {
    const float* z;
    const float* emb;
    if (in_sizes[0] == 524288) {
        z = (const float*)d_in[0];
        emb = (const float*)d_in[1];
    } else {
        z = (const float*)d_in[1];
        emb = (const float*)d_in[0];
    }
    float* out = (float*)d_out;

    static int attr_set = 0;
    if (!attr_set) {
        cudaFuncSetAttribute(vq_argmin, cudaFuncAttributeMaxDynamicSharedMemorySize,
                             SM_FLOATS * (int)sizeof(float));
        attr_set = 1;
    }

    vq_init<<<(NCODES + 255) / 256, 256>>>(out);
    vq_transpose<<<dim3(NCODES / 32, DIM / 32), dim3(32, 8)>>>(emb);
    vq_codenorm<<<(NCODES + 255) / 256, 256>>>(emb);
    vq_argmin<<<NPTS / PB, 256, SM_FLOATS * sizeof(float)>>>(z, emb, out);
    vq_finalize<<<1, 512>>>(out);
}